// round 12
// baseline (speedup 1.0000x reference)
#include <cuda_runtime.h>
#include <cuda_bf16.h>
#include <cstdint>
#include <cstddef>

#define NN   50000
#define EE   800000
#define INC  512
#define HIDC 256
#define OUTC 40
#define BN_EPS 1e-5f
#define NP   196        // ceil(NN/256) scan partials

// ---------------- scratch (device globals; no allocation allowed) ----------------
__device__ float g_deg[NN];
__device__ float g_dinv[NN];
__device__ int   g_cnt[NN];
__device__ int   g_rowstart[NN + 1];
__device__ int   g_cursor[NN];
__device__ int   g_part[NP];
__device__ int   g_partscan[NP];
__device__ int   g_ecol[EE];
__device__ float g_ew2[EE];          // w * dinv[col]  (sorted by row)
__device__ float g_t1[NN * HIDC];
__device__ float g_t2[NN * HIDC];
__device__ float g_t3[NN * OUTC];
__device__ float g_la[NN * OUTC];
__device__ float g_lb[NN * OUTC];
__device__ float g_lc[NN * OUTC];
__device__ float g_ld[NN * OUTC];
__device__ float g_sum0[HIDC];
__device__ float g_sumsq0[HIDC];
__device__ float g_sum1[HIDC];
__device__ float g_sumsq1[HIDC];
__device__ float g_scale[HIDC];
__device__ float g_shift[HIDC];
__device__ int   g_tick0;
__device__ int   g_tick1;
// pre-split bf16 hi/lo weights
__device__ __nv_bfloat16 g_w0h[INC * HIDC];
__device__ __nv_bfloat16 g_w0l[INC * HIDC];
__device__ __nv_bfloat16 g_w1h[HIDC * HIDC];
__device__ __nv_bfloat16 g_w1l[HIDC * HIDC];
__device__ __nv_bfloat16 g_w2h[HIDC * OUTC];
__device__ __nv_bfloat16 g_w2l[HIDC * OUTC];

// ---------------- weight split (variant 0 also initializes node arrays) ----------------
__global__ void k_split_w0(const float* __restrict__ W,
                           __nv_bfloat16* __restrict__ Wh,
                           __nv_bfloat16* __restrict__ Wl, int n) {
    int i = blockIdx.x * blockDim.x + threadIdx.x;
    if (i < NN) { g_deg[i] = 1.0f; g_cnt[i] = 0; }   // fused node init (self-loop weight)
    if (i < n) {
        float x = W[i];
        __nv_bfloat16 h = __float2bfloat16_rn(x);
        Wh[i] = h;
        Wl[i] = __float2bfloat16_rn(x - __bfloat162float(h));
    }
}

__global__ void k_split_w(const float* __restrict__ W,
                          __nv_bfloat16* __restrict__ Wh,
                          __nv_bfloat16* __restrict__ Wl, int n) {
    int i = blockIdx.x * blockDim.x + threadIdx.x;
    if (i < n) {
        float x = W[i];
        __nv_bfloat16 h = __float2bfloat16_rn(x);
        Wh[i] = h;
        Wl[i] = __float2bfloat16_rn(x - __bfloat162float(h));
    }
}

// ---------------- CSR construction ----------------
__global__ void k_deg_cnt(const int* __restrict__ row, const float* __restrict__ w) {
    int e = blockIdx.x * blockDim.x + threadIdx.x;
    if (e < EE) {
        int r = row[e];
        atomicAdd(&g_deg[r], w[e]);
        atomicAdd(&g_cnt[r], 1);
    }
}

// -------- 3-phase parallel scan (scan1 computes dinv; scan2 zeroes BN sums/tickets) --------
__device__ __forceinline__ int block_incl_scan(int val, int* warp_sums) {
    int lane = threadIdx.x & 31, wid = threadIdx.x >> 5;
    int v = val;
#pragma unroll
    for (int o = 1; o < 32; o <<= 1) {
        int n = __shfl_up_sync(0xffffffffu, v, o);
        if (lane >= o) v += n;
    }
    if (lane == 31) warp_sums[wid] = v;
    __syncthreads();
    if (wid == 0) {
        int w = (lane < 8) ? warp_sums[lane] : 0;
#pragma unroll
        for (int o = 1; o < 8; o <<= 1) {
            int n = __shfl_up_sync(0xffffffffu, w, o);
            if (lane >= o) w += n;
        }
        if (lane < 8) warp_sums[lane] = w;
    }
    __syncthreads();
    return v + (wid > 0 ? warp_sums[wid - 1] : 0);
}

__global__ void k_scan1() {
    __shared__ int ws[8];
    int i = blockIdx.x * 256 + threadIdx.x;
    if (i < NN) {                           // fused dinv
        float d = g_deg[i];
        g_dinv[i] = d > 0.f ? rsqrtf(fmaxf(d, 1e-12f)) : 0.f;
    }
    int val = (i < NN) ? g_cnt[i] : 0;
    int incl = block_incl_scan(val, ws);
    if (threadIdx.x == 255) g_part[blockIdx.x] = incl;
}

__global__ void k_scan2() {
    __shared__ int ws[8];
    int t = threadIdx.x;
    g_sum0[t] = 0.f; g_sumsq0[t] = 0.f;     // fused BN-stat zeroing (both layers)
    g_sum1[t] = 0.f; g_sumsq1[t] = 0.f;
    if (t == 0) { g_tick0 = 0; g_tick1 = 0; }
    int val = (t < NP) ? g_part[t] : 0;
    int incl = block_incl_scan(val, ws);
    if (t < NP) g_partscan[t] = incl - val;   // exclusive
}

__global__ void k_scan3() {
    __shared__ int ws[8];
    int i = blockIdx.x * 256 + threadIdx.x;
    int val = (i < NN) ? g_cnt[i] : 0;
    int incl = block_incl_scan(val, ws);
    int excl = incl - val + g_partscan[blockIdx.x];
    if (i < NN) { g_rowstart[i] = excl; g_cursor[i] = excl; }
    if (i == 0) g_rowstart[NN] = EE;
}

__global__ void k_scatter(const int* __restrict__ row, const int* __restrict__ col,
                          const float* __restrict__ w) {
    int e = blockIdx.x * blockDim.x + threadIdx.x;
    if (e < EE) {
        int r = row[e];
        int c = col[e];
        int pos = atomicAdd(&g_cursor[r], 1);
        g_ecol[pos] = c;
        g_ew2[pos] = w[e] * g_dinv[c];
    }
}

// ---------------- propagate C=256: block per node, float4 lanes x 4 edge slots ----------------
__global__ void __launch_bounds__(256) k_prop256(const float* __restrict__ h,
                                                 float* __restrict__ out,
                                                 const float* __restrict__ bias) {
    int i = blockIdx.x;
    int lane = threadIdx.x & 63;
    int slot = threadIdx.x >> 6;
    __shared__ int scol[256];
    __shared__ float sw[256];
    __shared__ float4 red[3][64];

    const float4* h4 = (const float4*)h;
    int s = g_rowstart[i], e = g_rowstart[i + 1];
    float4 acc = make_float4(0.f, 0.f, 0.f, 0.f);

    for (int base = s; base < e; base += 256) {
        int n = e - base; if (n > 256) n = 256;
        if (threadIdx.x < n) {
            scol[threadIdx.x] = g_ecol[base + threadIdx.x];
            sw[threadIdx.x]   = g_ew2[base + threadIdx.x];
        }
        __syncthreads();
        int j = slot;
        for (; j + 4 < n; j += 8) {       // 2 independent loads in flight
            float w0 = sw[j];
            float4 v0 = h4[(size_t)scol[j] * 64 + lane];
            float w1 = sw[j + 4];
            float4 v1 = h4[(size_t)scol[j + 4] * 64 + lane];
            acc.x += w0 * v0.x; acc.y += w0 * v0.y;
            acc.z += w0 * v0.z; acc.w += w0 * v0.w;
            acc.x += w1 * v1.x; acc.y += w1 * v1.y;
            acc.z += w1 * v1.z; acc.w += w1 * v1.w;
        }
        if (j < n) {
            float w0 = sw[j];
            float4 v0 = h4[(size_t)scol[j] * 64 + lane];
            acc.x += w0 * v0.x; acc.y += w0 * v0.y;
            acc.z += w0 * v0.z; acc.w += w0 * v0.w;
        }
        __syncthreads();
    }

    if (slot > 0) red[slot - 1][lane] = acc;
    __syncthreads();
    if (slot == 0) {
#pragma unroll
        for (int q = 0; q < 3; q++) {
            float4 r = red[q][lane];
            acc.x += r.x; acc.y += r.y; acc.z += r.z; acc.w += r.w;
        }
        float di = g_dinv[i];
        float dd = di * di;
        float4 hc = h4[(size_t)i * 64 + lane];
        float4 b = ((const float4*)bias)[lane];
        float4 o;
        o.x = dd * hc.x + di * acc.x + b.x;
        o.y = dd * hc.y + di * acc.y + b.y;
        o.z = dd * hc.z + di * acc.z + b.z;
        o.w = dd * hc.w + di * acc.w + b.w;
        ((float4*)out)[(size_t)i * 64 + lane] = o;
    }
}

// ---------------- propagate C=40: warp per node (R7 scalar form) ----------------
template <bool DUAL>
__global__ void __launch_bounds__(256) k_prop40(const float* __restrict__ ha,
                                                const float* __restrict__ hb,
                                                float* __restrict__ oa,
                                                float* __restrict__ ob,
                                                const float* __restrict__ bias) {
    int warp = threadIdx.x >> 5;
    int lane = threadIdx.x & 31;
    int i = blockIdx.x * 8 + warp;
    if (i >= NN) return;

    int s = g_rowstart[i], e = g_rowstart[i + 1];
    float a0 = 0.f, a1 = 0.f, b0 = 0.f, b1 = 0.f;

    for (int p = s; p < e; p++) {
        int c = g_ecol[p];
        float w = g_ew2[p];
        const float* ra = ha + (size_t)c * OUTC;
        a0 += w * ra[lane];
        if (lane < 8) a1 += w * ra[lane + 32];
        if (DUAL) {
            const float* rb = hb + (size_t)c * OUTC;
            b0 += w * rb[lane];
            if (lane < 8) b1 += w * rb[lane + 32];
        }
    }
    float di = g_dinv[i];
    size_t off = (size_t)i * OUTC;
    float bs0 = bias ? bias[lane] : 0.f;
    float bs1 = (bias && lane < 8) ? bias[lane + 32] : 0.f;

    oa[off + lane] = di * di * ha[off + lane] + di * a0 + bs0;
    if (lane < 8)
        oa[off + lane + 32] = di * di * ha[off + lane + 32] + di * a1 + bs1;
    if (DUAL) {
        ob[off + lane] = di * di * hb[off + lane] + di * b0;
        if (lane < 8)
            ob[off + lane + 32] = di * di * hb[off + lane + 32] + di * b1;
    }
}

// ---------------- batchnorm: reduce + last-block finalize (fused) ----------------
__global__ void k_bn_reduce(const float* __restrict__ h,
                            float* __restrict__ sum, float* __restrict__ sumsq,
                            const float* __restrict__ gamma, const float* __restrict__ beta,
                            int* __restrict__ ticket) {
    int c = threadIdx.x;
    float s = 0.f, sq = 0.f;
    for (int i = blockIdx.x; i < NN; i += gridDim.x) {
        float v = h[((size_t)i << 8) + c];
        s += v;
        sq += v * v;
    }
    atomicAdd(&sum[c], s);
    atomicAdd(&sumsq[c], sq);
    __threadfence();
    __shared__ int lastFlag;
    if (c == 0) lastFlag = (atomicAdd(ticket, 1) == (int)gridDim.x - 1);
    __syncthreads();
    if (lastFlag) {
        float ts = atomicAdd(&sum[c], 0.f);      // L2-coherent read
        float tq = atomicAdd(&sumsq[c], 0.f);
        float mean = ts * (1.0f / NN);
        float var = tq * (1.0f / NN) - mean * mean;
        var = fmaxf(var, 0.f);
        float inv = rsqrtf(var + BN_EPS);
        float sc = gamma[c] * inv;
        g_scale[c] = sc;
        g_shift[c] = beta[c] - mean * sc;
    }
}

// ---------------- bf16x3 split tensor-core GEMM (single-buffer, BK=32, pre-split B) ----------------
#define AS_ST 40    // bf16 units per A row (32 data + 8 pad): 80B rows, conflict-free ldmatrix
#define BS_ST 136   // bf16 units per B k-row (128 data + 8 pad)

__device__ __forceinline__ void ldsm_x4(uint32_t* r, uint32_t addr) {
    asm volatile("ldmatrix.sync.aligned.m8n8.x4.shared.b16 {%0,%1,%2,%3}, [%4];"
                 : "=r"(r[0]), "=r"(r[1]), "=r"(r[2]), "=r"(r[3]) : "r"(addr));
}
__device__ __forceinline__ void ldsm_x2_t(uint32_t* r, uint32_t addr) {
    asm volatile("ldmatrix.sync.aligned.m8n8.x2.trans.shared.b16 {%0,%1}, [%2];"
                 : "=r"(r[0]), "=r"(r[1]) : "r"(addr));
}
__device__ __forceinline__ void mma_bf16(float* c, const uint32_t* a, const uint32_t* b) {
    asm volatile(
        "mma.sync.aligned.m16n8k16.row.col.f32.bf16.bf16.f32 "
        "{%0,%1,%2,%3}, {%4,%5,%6,%7}, {%8,%9}, {%0,%1,%2,%3};"
        : "+f"(c[0]), "+f"(c[1]), "+f"(c[2]), "+f"(c[3])
        : "r"(a[0]), "r"(a[1]), "r"(a[2]), "r"(a[3]), "r"(b[0]), "r"(b[1]));
}

__device__ __forceinline__ void split_bf16(float x, __nv_bfloat16& h, __nv_bfloat16& l) {
    h = __float2bfloat16_rn(x);
    l = __float2bfloat16_rn(x - __bfloat162float(h));
}

template <bool FUSE_BN>
__global__ void __launch_bounds__(256) k_mma_bf16(int M, int N, int K,
                                                  const float* __restrict__ A,
                                                  const __nv_bfloat16* __restrict__ Bh_g,
                                                  const __nv_bfloat16* __restrict__ Bl_g,
                                                  float* __restrict__ C) {
    __shared__ __nv_bfloat16 Ah[128 * AS_ST];
    __shared__ __nv_bfloat16 Al[128 * AS_ST];
    __shared__ __nv_bfloat16 Bh[32 * BS_ST];
    __shared__ __nv_bfloat16 Bl[32 * BS_ST];

    int tid = threadIdx.x;
    int bm = blockIdx.y * 128, bn = blockIdx.x * 128;

    int aRow = tid >> 1;            // 0..127
    int aK   = (tid & 1) * 16;      // 0 or 16 (4 float4 each)
    int bK   = tid >> 4;            // 0..15 (also handles row bK+16)
    int bN   = (tid & 15) * 8;      // 0..120

    int warp = tid >> 5, lane = tid & 31;
    int wm = (warp >> 1) * 32;
    int wn = (warp & 1) * 64;
    int groupID = lane >> 2, tig = lane & 3;

    uint32_t sAh = (uint32_t)__cvta_generic_to_shared(Ah);
    uint32_t sAl = (uint32_t)__cvta_generic_to_shared(Al);
    uint32_t sBh = (uint32_t)__cvta_generic_to_shared(Bh);
    uint32_t sBl = (uint32_t)__cvta_generic_to_shared(Bl);

    uint32_t aAddrH[2], aAddrL[2];
#pragma unroll
    for (int mi = 0; mi < 2; mi++) {
        int ar = wm + mi * 16 + (lane & 7) + ((lane >> 3) & 1) * 8;
        int ako = (lane & 16) ? 8 : 0;
        uint32_t off = (uint32_t)(ar * AS_ST + ako) * 2;
        aAddrH[mi] = sAh + off;
        aAddrL[mi] = sAl + off;
    }
    int bk = ((lane & 15) >> 3) * 8 + (lane & 7);
    uint32_t bRowOffH = sBh + (uint32_t)(bk * BS_ST) * 2;
    uint32_t bRowOffL = sBl + (uint32_t)(bk * BS_ST) * 2;

    float acc[2][8][4];
#pragma unroll
    for (int mi = 0; mi < 2; mi++)
#pragma unroll
        for (int ni = 0; ni < 8; ni++)
#pragma unroll
            for (int q = 0; q < 4; q++) acc[mi][ni][q] = 0.f;

    int grow = bm + aRow;
    int gn = bn + bN;
    bool bIn = (gn + 8 <= N);       // N is a multiple of 8 here

    // ---- prefetch tile 0 into registers ----
    float4 aPf[4];
    uint4 bhPf[2], blPf[2];
    {
#pragma unroll
        for (int q = 0; q < 4; q++) {
            aPf[q] = make_float4(0.f, 0.f, 0.f, 0.f);
            if (grow < M) aPf[q] = *(const float4*)(A + (size_t)grow * K + aK + q * 4);
        }
#pragma unroll
        for (int r = 0; r < 2; r++) {
            bhPf[r] = make_uint4(0, 0, 0, 0);
            blPf[r] = make_uint4(0, 0, 0, 0);
            if (bIn) {
                bhPf[r] = *(const uint4*)(Bh_g + (size_t)(bK + r * 16) * N + gn);
                blPf[r] = *(const uint4*)(Bl_g + (size_t)(bK + r * 16) * N + gn);
            }
        }
    }

    for (int k0 = 0; k0 < K; k0 += 32) {
        // ---- convert + store current tile to smem ----
#pragma unroll
        for (int q = 0; q < 4; q++) {
            float4 v = aPf[q];
            if (FUSE_BN) {
                int k = k0 + aK + q * 4;
                v.x = fmaxf(v.x * g_scale[k + 0] + g_shift[k + 0], 0.f);
                v.y = fmaxf(v.y * g_scale[k + 1] + g_shift[k + 1], 0.f);
                v.z = fmaxf(v.z * g_scale[k + 2] + g_shift[k + 2], 0.f);
                v.w = fmaxf(v.w * g_scale[k + 3] + g_shift[k + 3], 0.f);
            }
            __nv_bfloat16 h0, l0, h1, l1, h2, l2, h3, l3;
            split_bf16(v.x, h0, l0); split_bf16(v.y, h1, l1);
            split_bf16(v.z, h2, l2); split_bf16(v.w, h3, l3);
            int off = aRow * AS_ST + aK + q * 4;
            *(__nv_bfloat162*)(Ah + off)     = __nv_bfloat162(h0, h1);
            *(__nv_bfloat162*)(Ah + off + 2) = __nv_bfloat162(h2, h3);
            *(__nv_bfloat162*)(Al + off)     = __nv_bfloat162(l0, l1);
            *(__nv_bfloat162*)(Al + off + 2) = __nv_bfloat162(l2, l3);
        }
#pragma unroll
        for (int r = 0; r < 2; r++) {
            *(uint4*)(&Bh[(bK + r * 16) * BS_ST + bN]) = bhPf[r];
            *(uint4*)(&Bl[(bK + r * 16) * BS_ST + bN]) = blPf[r];
        }
        __syncthreads();

        // ---- prefetch next tile into registers (hidden behind mma) ----
        if (k0 + 32 < K) {
            int k0n = k0 + 32;
#pragma unroll
            for (int q = 0; q < 4; q++) {
                aPf[q] = make_float4(0.f, 0.f, 0.f, 0.f);
                if (grow < M) aPf[q] = *(const float4*)(A + (size_t)grow * K + k0n + aK + q * 4);
            }
#pragma unroll
            for (int r = 0; r < 2; r++) {
                if (bIn) {
                    bhPf[r] = *(const uint4*)(Bh_g + (size_t)(k0n + bK + r * 16) * N + gn);
                    blPf[r] = *(const uint4*)(Bl_g + (size_t)(k0n + bK + r * 16) * N + gn);
                }
            }
        }

        // ---- fragments + mma: two k-steps per staged tile ----
#pragma unroll
        for (int ks = 0; ks < 2; ks++) {
            uint32_t aOff = ks * 32;                          // +16 bf16 columns
            uint32_t bOff = (uint32_t)(ks * 16 * BS_ST) * 2;  // +16 k-rows
            uint32_t ah[2][4], al[2][4];
#pragma unroll
            for (int mi = 0; mi < 2; mi++) {
                ldsm_x4(ah[mi], aAddrH[mi] + aOff);
                ldsm_x4(al[mi], aAddrL[mi] + aOff);
            }
#pragma unroll
            for (int ni = 0; ni < 8; ni++) {
                uint32_t coff = (uint32_t)(wn + ni * 8) * 2;
                uint32_t bh2[2], bl2[2];
                ldsm_x2_t(bh2, bRowOffH + bOff + coff);
                ldsm_x2_t(bl2, bRowOffL + bOff + coff);
#pragma unroll
                for (int mi = 0; mi < 2; mi++) {
                    mma_bf16(acc[mi][ni], ah[mi], bh2);
                    mma_bf16(acc[mi][ni], al[mi], bh2);
                    mma_bf16(acc[mi][ni], ah[mi], bl2);
                }
            }
        }
        __syncthreads();
    }

    // ---- store C ----
#pragma unroll
    for (int mi = 0; mi < 2; mi++) {
        int r0 = bm + wm + mi * 16 + groupID;
        int r1 = r0 + 8;
#pragma unroll
        for (int ni = 0; ni < 8; ni++) {
            int c0 = bn + wn + ni * 8 + 2 * tig;
            if (r0 < M) {
                if (c0 < N)     C[(size_t)r0 * N + c0]     = acc[mi][ni][0];
                if (c0 + 1 < N) C[(size_t)r0 * N + c0 + 1] = acc[mi][ni][1];
            }
            if (r1 < M) {
                if (c0 < N)     C[(size_t)r1 * N + c0]     = acc[mi][ni][2];
                if (c0 + 1 < N) C[(size_t)r1 * N + c0 + 1] = acc[mi][ni][3];
            }
        }
    }
}

// ---------------- host orchestration ----------------
static inline int cdiv(int a, int b) { return (a + b - 1) / b; }

extern "C" void kernel_launch(void* const* d_in, const int* in_sizes, int n_in,
                              void* d_out, int out_size) {
    const float* x    = (const float*)d_in[0];
    const int*   ei   = (const int*)  d_in[1];
    const float* lab  = (const float*)d_in[2];
    const float* lab2 = (const float*)d_in[3];
    const float* ew   = (const float*)d_in[4];
    const float* W0   = (const float*)d_in[5];
    const float* b0   = (const float*)d_in[6];
    const float* W1   = (const float*)d_in[7];
    const float* b1   = (const float*)d_in[8];
    const float* W2   = (const float*)d_in[9];
    const float* b2   = (const float*)d_in[10];
    const float* g0   = (const float*)d_in[11];
    const float* be0  = (const float*)d_in[12];
    const float* g1   = (const float*)d_in[13];
    const float* be1  = (const float*)d_in[14];
    float* out = (float*)d_out;

    const int* row = ei;
    const int* col = ei + EE;

    float *t1, *t2, *t3, *la, *lb, *lc, *ld;
    float *sum0, *sumsq0, *sum1, *sumsq1;
    int *tick0, *tick1;
    __nv_bfloat16 *w0h, *w0l, *w1h, *w1l, *w2h, *w2l;
    cudaGetSymbolAddress((void**)&t1, g_t1);
    cudaGetSymbolAddress((void**)&t2, g_t2);
    cudaGetSymbolAddress((void**)&t3, g_t3);
    cudaGetSymbolAddress((void**)&la, g_la);
    cudaGetSymbolAddress((void**)&lb, g_lb);
    cudaGetSymbolAddress((void**)&lc, g_lc);
    cudaGetSymbolAddress((void**)&ld, g_ld);
    cudaGetSymbolAddress((void**)&sum0,   g_sum0);
    cudaGetSymbolAddress((void**)&sumsq0, g_sumsq0);
    cudaGetSymbolAddress((void**)&sum1,   g_sum1);
    cudaGetSymbolAddress((void**)&sumsq1, g_sumsq1);
    cudaGetSymbolAddress((void**)&tick0, g_tick0);
    cudaGetSymbolAddress((void**)&tick1, g_tick1);
    cudaGetSymbolAddress((void**)&w0h, g_w0h);
    cudaGetSymbolAddress((void**)&w0l, g_w0l);
    cudaGetSymbolAddress((void**)&w1h, g_w1h);
    cudaGetSymbolAddress((void**)&w1l, g_w1l);
    cudaGetSymbolAddress((void**)&w2h, g_w2h);
    cudaGetSymbolAddress((void**)&w2l, g_w2l);

    const int T = 256;
    float* yh1 = out + (size_t)NN * OUTC;
    float* yh2 = out + (size_t)2 * NN * OUTC;

    // ---- weight pre-split (first also inits node arrays) ----
    k_split_w0<<<cdiv(INC * HIDC, T), T>>>(W0, w0h, w0l, INC * HIDC);
    k_split_w<<<cdiv(HIDC * HIDC, T), T>>>(W1, w1h, w1l, HIDC * HIDC);
    k_split_w<<<cdiv(HIDC * OUTC, T), T>>>(W2, w2h, w2l, HIDC * OUTC);

    // ---- CSR + normalization ----
    k_deg_cnt<<<cdiv(EE, T), T>>>(row, ew);
    k_scan1<<<NP, 256>>>();                  // + dinv
    k_scan2<<<1, 256>>>();                   // + zero BN stats & tickets
    k_scan3<<<NP, 256>>>();
    k_scatter<<<cdiv(EE, T), T>>>(row, col, ew);

    dim3 gemm_grid_hid(2, cdiv(NN, 128));   // N=256
    dim3 gemm_grid_out(1, cdiv(NN, 128));   // N=40
    int prop40_grid = cdiv(NN, 8);

    // ---- layer 0: x@W0 -> propagate(+b0) -> BN stats (+ fused finalize) ----
    k_mma_bf16<false><<<gemm_grid_hid, T>>>(NN, HIDC, INC, x, w0h, w0l, t1);
    k_prop256<<<NN, 256>>>(t1, t2, b0);
    k_bn_reduce<<<256, HIDC>>>(t2, sum0, sumsq0, g0, be0, tick0);

    // ---- layer 1: relu(bn(t2))@W1 -> propagate(+b1) -> BN stats (+ finalize) ----
    k_mma_bf16<true><<<gemm_grid_hid, T>>>(NN, HIDC, HIDC, t2, w1h, w1l, t1);
    k_prop256<<<NN, 256>>>(t1, t2, b1);
    k_bn_reduce<<<256, HIDC>>>(t2, sum1, sumsq1, g1, be1, tick1);

    // ---- output conv: relu(bn(t2))@W2 -> propagate(+b2) -> d_out ----
    k_mma_bf16<true><<<gemm_grid_out, T>>>(NN, OUTC, HIDC, t2, w2h, w2l, t3);
    k_prop40<false><<<prop40_grid, 256>>>(t3, nullptr, out, nullptr, b2);

    // ---- LPA: 3 dual propagates ----
    k_prop40<true><<<prop40_grid, 256>>>(lab, lab2, la, lb, nullptr);
    k_prop40<true><<<prop40_grid, 256>>>(la, lb, lc, ld, nullptr);
    k_prop40<true><<<prop40_grid, 256>>>(lc, ld, yh1, yh2, nullptr);
}

// round 16
// speedup vs baseline: 1.2314x; 1.2314x over previous
#include <cuda_runtime.h>
#include <cuda_bf16.h>
#include <cstdint>
#include <cstddef>

#define NN   50000
#define EE   800000
#define INC  512
#define HIDC 256
#define OUTC 40
#define BN_EPS 1e-5f
#define NP   196        // ceil(NN/256) scan partials
#define BN_GRID 1024

// ---------------- scratch (device globals; no allocation allowed) ----------------
__device__ float g_deg[NN];
__device__ float g_dinv[NN];
__device__ int   g_cnt[NN];
__device__ int   g_rowstart[NN + 1];
__device__ int   g_cursor[NN];
__device__ int   g_part[NP];
__device__ int   g_partscan[NP];
__device__ int   g_ecol[EE];
__device__ float g_ew2[EE];          // w * dinv[col]  (sorted by row)
__device__ float g_t1[NN * HIDC];
__device__ float g_t2[NN * HIDC];
__device__ float g_t3[NN * OUTC];
__device__ float g_la[NN * OUTC];
__device__ float g_lb[NN * OUTC];
__device__ float g_lc[NN * OUTC];
__device__ float g_ld[NN * OUTC];
__device__ float g_sum0[HIDC];
__device__ float g_sumsq0[HIDC];
__device__ float g_sum1[HIDC];
__device__ float g_sumsq1[HIDC];
__device__ float g_scale[HIDC];
__device__ float g_shift[HIDC];
__device__ int   g_tick0;
__device__ int   g_tick1;
// pre-split bf16 hi/lo weights
__device__ __nv_bfloat16 g_w0h[INC * HIDC];
__device__ __nv_bfloat16 g_w0l[INC * HIDC];
__device__ __nv_bfloat16 g_w1h[HIDC * HIDC];
__device__ __nv_bfloat16 g_w1l[HIDC * HIDC];
__device__ __nv_bfloat16 g_w2h[HIDC * OUTC];
__device__ __nv_bfloat16 g_w2l[HIDC * OUTC];

// ---------------- weight split ----------------
__global__ void k_split_w(const float* __restrict__ W,
                          __nv_bfloat16* __restrict__ Wh,
                          __nv_bfloat16* __restrict__ Wl, int n) {
    int i = blockIdx.x * blockDim.x + threadIdx.x;
    if (i < n) {
        float x = W[i];
        __nv_bfloat16 h = __float2bfloat16_rn(x);
        Wh[i] = h;
        Wl[i] = __float2bfloat16_rn(x - __bfloat162float(h));
    }
}

// ---------------- CSR construction ----------------
__global__ void k_init_node() {
    int i = blockIdx.x * blockDim.x + threadIdx.x;
    if (i < NN) { g_deg[i] = 1.0f; g_cnt[i] = 0; }   // self-loop weight
}

__global__ void k_deg_cnt(const int* __restrict__ row, const float* __restrict__ w) {
    int e = blockIdx.x * blockDim.x + threadIdx.x;
    if (e < EE) {
        int r = row[e];
        atomicAdd(&g_deg[r], w[e]);
        atomicAdd(&g_cnt[r], 1);
    }
}

// -------- 3-phase parallel scan (scan1 computes dinv; scan2 zeroes BN sums/tickets) --------
__device__ __forceinline__ int block_incl_scan(int val, int* warp_sums) {
    int lane = threadIdx.x & 31, wid = threadIdx.x >> 5;
    int v = val;
#pragma unroll
    for (int o = 1; o < 32; o <<= 1) {
        int n = __shfl_up_sync(0xffffffffu, v, o);
        if (lane >= o) v += n;
    }
    if (lane == 31) warp_sums[wid] = v;
    __syncthreads();
    if (wid == 0) {
        int w = (lane < 8) ? warp_sums[lane] : 0;
#pragma unroll
        for (int o = 1; o < 8; o <<= 1) {
            int n = __shfl_up_sync(0xffffffffu, w, o);
            if (lane >= o) w += n;
        }
        if (lane < 8) warp_sums[lane] = w;
    }
    __syncthreads();
    return v + (wid > 0 ? warp_sums[wid - 1] : 0);
}

__global__ void k_scan1() {
    __shared__ int ws[8];
    int i = blockIdx.x * 256 + threadIdx.x;
    if (i < NN) {                           // fused dinv
        float d = g_deg[i];
        g_dinv[i] = d > 0.f ? rsqrtf(fmaxf(d, 1e-12f)) : 0.f;
    }
    int val = (i < NN) ? g_cnt[i] : 0;
    int incl = block_incl_scan(val, ws);
    if (threadIdx.x == 255) g_part[blockIdx.x] = incl;
}

__global__ void k_scan2() {
    __shared__ int ws[8];
    int t = threadIdx.x;
    g_sum0[t] = 0.f; g_sumsq0[t] = 0.f;     // fused BN-stat zeroing (both layers)
    g_sum1[t] = 0.f; g_sumsq1[t] = 0.f;
    if (t == 0) { g_tick0 = 0; g_tick1 = 0; }
    int val = (t < NP) ? g_part[t] : 0;
    int incl = block_incl_scan(val, ws);
    if (t < NP) g_partscan[t] = incl - val;   // exclusive
}

__global__ void k_scan3() {
    __shared__ int ws[8];
    int i = blockIdx.x * 256 + threadIdx.x;
    int val = (i < NN) ? g_cnt[i] : 0;
    int incl = block_incl_scan(val, ws);
    int excl = incl - val + g_partscan[blockIdx.x];
    if (i < NN) { g_rowstart[i] = excl; g_cursor[i] = excl; }
    if (i == 0) g_rowstart[NN] = EE;
}

__global__ void k_scatter(const int* __restrict__ row, const int* __restrict__ col,
                          const float* __restrict__ w) {
    int e = blockIdx.x * blockDim.x + threadIdx.x;
    if (e < EE) {
        int r = row[e];
        int c = col[e];
        int pos = atomicAdd(&g_cursor[r], 1);
        g_ecol[pos] = c;
        g_ew2[pos] = w[e] * g_dinv[c];
    }
}

// ---------------- propagate C=256: block per node, float4 lanes x 4 edge slots ----------------
__global__ void __launch_bounds__(256) k_prop256(const float* __restrict__ h,
                                                 float* __restrict__ out,
                                                 const float* __restrict__ bias) {
    int i = blockIdx.x;
    int lane = threadIdx.x & 63;
    int slot = threadIdx.x >> 6;
    __shared__ int scol[256];
    __shared__ float sw[256];
    __shared__ float4 red[3][64];

    const float4* h4 = (const float4*)h;
    int s = g_rowstart[i], e = g_rowstart[i + 1];
    float4 acc = make_float4(0.f, 0.f, 0.f, 0.f);

    for (int base = s; base < e; base += 256) {
        int n = e - base; if (n > 256) n = 256;
        if (threadIdx.x < n) {
            scol[threadIdx.x] = g_ecol[base + threadIdx.x];
            sw[threadIdx.x]   = g_ew2[base + threadIdx.x];
        }
        __syncthreads();
        int j = slot;
        for (; j + 4 < n; j += 8) {       // 2 independent loads in flight
            float w0 = sw[j];
            float4 v0 = h4[(size_t)scol[j] * 64 + lane];
            float w1 = sw[j + 4];
            float4 v1 = h4[(size_t)scol[j + 4] * 64 + lane];
            acc.x += w0 * v0.x; acc.y += w0 * v0.y;
            acc.z += w0 * v0.z; acc.w += w0 * v0.w;
            acc.x += w1 * v1.x; acc.y += w1 * v1.y;
            acc.z += w1 * v1.z; acc.w += w1 * v1.w;
        }
        if (j < n) {
            float w0 = sw[j];
            float4 v0 = h4[(size_t)scol[j] * 64 + lane];
            acc.x += w0 * v0.x; acc.y += w0 * v0.y;
            acc.z += w0 * v0.z; acc.w += w0 * v0.w;
        }
        __syncthreads();
    }

    if (slot > 0) red[slot - 1][lane] = acc;
    __syncthreads();
    if (slot == 0) {
#pragma unroll
        for (int q = 0; q < 3; q++) {
            float4 r = red[q][lane];
            acc.x += r.x; acc.y += r.y; acc.z += r.z; acc.w += r.w;
        }
        float di = g_dinv[i];
        float dd = di * di;
        float4 hc = h4[(size_t)i * 64 + lane];
        float4 b = ((const float4*)bias)[lane];
        float4 o;
        o.x = dd * hc.x + di * acc.x + b.x;
        o.y = dd * hc.y + di * acc.y + b.y;
        o.z = dd * hc.z + di * acc.z + b.z;
        o.w = dd * hc.w + di * acc.w + b.w;
        ((float4*)out)[(size_t)i * 64 + lane] = o;
    }
}

// ---------------- propagate C=40: warp per node (R7 scalar form) ----------------
template <bool DUAL>
__global__ void __launch_bounds__(256) k_prop40(const float* __restrict__ ha,
                                                const float* __restrict__ hb,
                                                float* __restrict__ oa,
                                                float* __restrict__ ob,
                                                const float* __restrict__ bias) {
    int warp = threadIdx.x >> 5;
    int lane = threadIdx.x & 31;
    int i = blockIdx.x * 8 + warp;
    if (i >= NN) return;

    int s = g_rowstart[i], e = g_rowstart[i + 1];
    float a0 = 0.f, a1 = 0.f, b0 = 0.f, b1 = 0.f;

    for (int p = s; p < e; p++) {
        int c = g_ecol[p];
        float w = g_ew2[p];
        const float* ra = ha + (size_t)c * OUTC;
        a0 += w * ra[lane];
        if (lane < 8) a1 += w * ra[lane + 32];
        if (DUAL) {
            const float* rb = hb + (size_t)c * OUTC;
            b0 += w * rb[lane];
            if (lane < 8) b1 += w * rb[lane + 32];
        }
    }
    float di = g_dinv[i];
    size_t off = (size_t)i * OUTC;
    float bs0 = bias ? bias[lane] : 0.f;
    float bs1 = (bias && lane < 8) ? bias[lane + 32] : 0.f;

    oa[off + lane] = di * di * ha[off + lane] + di * a0 + bs0;
    if (lane < 8)
        oa[off + lane + 32] = di * di * ha[off + lane + 32] + di * a1 + bs1;
    if (DUAL) {
        ob[off + lane] = di * di * hb[off + lane] + di * b0;
        if (lane < 8)
            ob[off + lane + 32] = di * di * hb[off + lane + 32] + di * b1;
    }
}

// ---------------- batchnorm: reduce + last-block finalize ----------------
// RACE FIX (R15 post-mortem): __syncthreads between each thread's fenced
// atomicAdds and the c==0 ticket increment. Without it, a block can be
// counted "arrived" while threads 1..255's partials are still in flight.
__global__ void k_bn_reduce(const float* __restrict__ h,
                            float* __restrict__ sum, float* __restrict__ sumsq,
                            const float* __restrict__ gamma, const float* __restrict__ beta,
                            int* __restrict__ ticket) {
    int c = threadIdx.x;
    float s = 0.f, sq = 0.f;
    for (int i = blockIdx.x; i < NN; i += gridDim.x) {
        float v = h[((size_t)i << 8) + c];
        s += v;
        sq += v * v;
    }
    atomicAdd(&sum[c], s);
    atomicAdd(&sumsq[c], sq);
    __threadfence();              // order THIS thread's adds globally
    __syncthreads();              // ALL threads' adds fenced before ticket
    __shared__ int lastFlag;
    if (c == 0) lastFlag = (atomicAdd(ticket, 1) == (int)gridDim.x - 1);
    __syncthreads();
    if (lastFlag) {
        float ts = atomicAdd(&sum[c], 0.f);      // L2-coherent read
        float tq = atomicAdd(&sumsq[c], 0.f);
        float mean = ts * (1.0f / NN);
        float var = tq * (1.0f / NN) - mean * mean;
        var = fmaxf(var, 0.f);
        float inv = rsqrtf(var + BN_EPS);
        float sc = gamma[c] * inv;
        g_scale[c] = sc;
        g_shift[c] = beta[c] - mean * sc;
    }
}

// ---------------- bf16x3 split tensor-core GEMM (single-buffer, pre-split B) ----------------
#define AS_ST 24    // bf16 units per A row (16 data + 8 pad)
#define BS_ST 136   // bf16 units per B k-row (128 data + 8 pad)

__device__ __forceinline__ void ldsm_x4(uint32_t* r, uint32_t addr) {
    asm volatile("ldmatrix.sync.aligned.m8n8.x4.shared.b16 {%0,%1,%2,%3}, [%4];"
                 : "=r"(r[0]), "=r"(r[1]), "=r"(r[2]), "=r"(r[3]) : "r"(addr));
}
__device__ __forceinline__ void ldsm_x2_t(uint32_t* r, uint32_t addr) {
    asm volatile("ldmatrix.sync.aligned.m8n8.x2.trans.shared.b16 {%0,%1}, [%2];"
                 : "=r"(r[0]), "=r"(r[1]) : "r"(addr));
}
__device__ __forceinline__ void mma_bf16(float* c, const uint32_t* a, const uint32_t* b) {
    asm volatile(
        "mma.sync.aligned.m16n8k16.row.col.f32.bf16.bf16.f32 "
        "{%0,%1,%2,%3}, {%4,%5,%6,%7}, {%8,%9}, {%0,%1,%2,%3};"
        : "+f"(c[0]), "+f"(c[1]), "+f"(c[2]), "+f"(c[3])
        : "r"(a[0]), "r"(a[1]), "r"(a[2]), "r"(a[3]), "r"(b[0]), "r"(b[1]));
}

__device__ __forceinline__ void split_bf16(float x, __nv_bfloat16& h, __nv_bfloat16& l) {
    h = __float2bfloat16_rn(x);
    l = __float2bfloat16_rn(x - __bfloat162float(h));
}

template <bool FUSE_BN>
__global__ void __launch_bounds__(256) k_mma_bf16(int M, int N, int K,
                                                  const float* __restrict__ A,
                                                  const __nv_bfloat16* __restrict__ Bh_g,
                                                  const __nv_bfloat16* __restrict__ Bl_g,
                                                  float* __restrict__ C) {
    __shared__ __nv_bfloat16 Ah[128 * AS_ST];
    __shared__ __nv_bfloat16 Al[128 * AS_ST];
    __shared__ __nv_bfloat16 Bh[16 * BS_ST];
    __shared__ __nv_bfloat16 Bl[16 * BS_ST];

    int tid = threadIdx.x;
    int bm = blockIdx.y * 128, bn = blockIdx.x * 128;

    int aRow = tid >> 1;            // 0..127
    int aK   = (tid & 1) * 8;       // 0 or 8
    int bK   = tid >> 4;            // 0..15
    int bN   = (tid & 15) * 8;      // 0..120

    int warp = tid >> 5, lane = tid & 31;
    int wm = (warp >> 1) * 32;
    int wn = (warp & 1) * 64;
    int groupID = lane >> 2, tig = lane & 3;

    uint32_t sAh = (uint32_t)__cvta_generic_to_shared(Ah);
    uint32_t sAl = (uint32_t)__cvta_generic_to_shared(Al);
    uint32_t sBh = (uint32_t)__cvta_generic_to_shared(Bh);
    uint32_t sBl = (uint32_t)__cvta_generic_to_shared(Bl);

    uint32_t aAddrH[2], aAddrL[2];
#pragma unroll
    for (int mi = 0; mi < 2; mi++) {
        int ar = wm + mi * 16 + (lane & 7) + ((lane >> 3) & 1) * 8;
        int ako = (lane & 16) ? 8 : 0;
        uint32_t off = (uint32_t)(ar * AS_ST + ako) * 2;
        aAddrH[mi] = sAh + off;
        aAddrL[mi] = sAl + off;
    }
    int bk = ((lane & 15) >> 3) * 8 + (lane & 7);
    uint32_t bRowOffH = sBh + (uint32_t)(bk * BS_ST) * 2;
    uint32_t bRowOffL = sBl + (uint32_t)(bk * BS_ST) * 2;

    float acc[2][8][4];
#pragma unroll
    for (int mi = 0; mi < 2; mi++)
#pragma unroll
        for (int ni = 0; ni < 8; ni++)
#pragma unroll
            for (int q = 0; q < 4; q++) acc[mi][ni][q] = 0.f;

    int grow = bm + aRow;
    int gn = bn + bN;
    bool bIn = (gn + 8 <= N);       // N is a multiple of 8 here

    // ---- prefetch tile 0 into registers ----
    float4 aPf[2];
    uint4 bhPf = make_uint4(0, 0, 0, 0), blPf = make_uint4(0, 0, 0, 0);
    {
#pragma unroll
        for (int q = 0; q < 2; q++) {
            aPf[q] = make_float4(0.f, 0.f, 0.f, 0.f);
            if (grow < M) aPf[q] = *(const float4*)(A + (size_t)grow * K + aK + q * 4);
        }
        if (bIn) {
            bhPf = *(const uint4*)(Bh_g + (size_t)bK * N + gn);
            blPf = *(const uint4*)(Bl_g + (size_t)bK * N + gn);
        }
    }

    for (int k0 = 0; k0 < K; k0 += 16) {
        // ---- convert + store current tile to smem ----
#pragma unroll
        for (int q = 0; q < 2; q++) {
            float4 v = aPf[q];
            if (FUSE_BN) {
                int k = k0 + aK + q * 4;
                v.x = fmaxf(v.x * g_scale[k + 0] + g_shift[k + 0], 0.f);
                v.y = fmaxf(v.y * g_scale[k + 1] + g_shift[k + 1], 0.f);
                v.z = fmaxf(v.z * g_scale[k + 2] + g_shift[k + 2], 0.f);
                v.w = fmaxf(v.w * g_scale[k + 3] + g_shift[k + 3], 0.f);
            }
            __nv_bfloat16 h0, l0, h1, l1, h2, l2, h3, l3;
            split_bf16(v.x, h0, l0); split_bf16(v.y, h1, l1);
            split_bf16(v.z, h2, l2); split_bf16(v.w, h3, l3);
            int off = aRow * AS_ST + aK + q * 4;
            *(__nv_bfloat162*)(Ah + off)     = __nv_bfloat162(h0, h1);
            *(__nv_bfloat162*)(Ah + off + 2) = __nv_bfloat162(h2, h3);
            *(__nv_bfloat162*)(Al + off)     = __nv_bfloat162(l0, l1);
            *(__nv_bfloat162*)(Al + off + 2) = __nv_bfloat162(l2, l3);
        }
        *(uint4*)(&Bh[bK * BS_ST + bN]) = bhPf;
        *(uint4*)(&Bl[bK * BS_ST + bN]) = blPf;
        __syncthreads();

        // ---- prefetch next tile into registers (hidden behind mma) ----
        if (k0 + 16 < K) {
            int k0n = k0 + 16;
#pragma unroll
            for (int q = 0; q < 2; q++) {
                aPf[q] = make_float4(0.f, 0.f, 0.f, 0.f);
                if (grow < M) aPf[q] = *(const float4*)(A + (size_t)grow * K + k0n + aK + q * 4);
            }
            if (bIn) {
                bhPf = *(const uint4*)(Bh_g + (size_t)(k0n + bK) * N + gn);
                blPf = *(const uint4*)(Bl_g + (size_t)(k0n + bK) * N + gn);
            }
        }

        // ---- fragments + mma ----
        uint32_t ah[2][4], al[2][4];
#pragma unroll
        for (int mi = 0; mi < 2; mi++) {
            ldsm_x4(ah[mi], aAddrH[mi]);
            ldsm_x4(al[mi], aAddrL[mi]);
        }
#pragma unroll
        for (int ni = 0; ni < 8; ni++) {
            uint32_t coff = (uint32_t)(wn + ni * 8) * 2;
            uint32_t bh2[2], bl2[2];
            ldsm_x2_t(bh2, bRowOffH + coff);
            ldsm_x2_t(bl2, bRowOffL + coff);
#pragma unroll
            for (int mi = 0; mi < 2; mi++) {
                mma_bf16(acc[mi][ni], ah[mi], bh2);
                mma_bf16(acc[mi][ni], al[mi], bh2);
                mma_bf16(acc[mi][ni], ah[mi], bl2);
            }
        }
        __syncthreads();
    }

    // ---- store C ----
#pragma unroll
    for (int mi = 0; mi < 2; mi++) {
        int r0 = bm + wm + mi * 16 + groupID;
        int r1 = r0 + 8;
#pragma unroll
        for (int ni = 0; ni < 8; ni++) {
            int c0 = bn + wn + ni * 8 + 2 * tig;
            if (r0 < M) {
                if (c0 < N)     C[(size_t)r0 * N + c0]     = acc[mi][ni][0];
                if (c0 + 1 < N) C[(size_t)r0 * N + c0 + 1] = acc[mi][ni][1];
            }
            if (r1 < M) {
                if (c0 < N)     C[(size_t)r1 * N + c0]     = acc[mi][ni][2];
                if (c0 + 1 < N) C[(size_t)r1 * N + c0 + 1] = acc[mi][ni][3];
            }
        }
    }
}

// ---------------- host orchestration ----------------
static inline int cdiv(int a, int b) { return (a + b - 1) / b; }

extern "C" void kernel_launch(void* const* d_in, const int* in_sizes, int n_in,
                              void* d_out, int out_size) {
    const float* x    = (const float*)d_in[0];
    const int*   ei   = (const int*)  d_in[1];
    const float* lab  = (const float*)d_in[2];
    const float* lab2 = (const float*)d_in[3];
    const float* ew   = (const float*)d_in[4];
    const float* W0   = (const float*)d_in[5];
    const float* b0   = (const float*)d_in[6];
    const float* W1   = (const float*)d_in[7];
    const float* b1   = (const float*)d_in[8];
    const float* W2   = (const float*)d_in[9];
    const float* b2   = (const float*)d_in[10];
    const float* g0   = (const float*)d_in[11];
    const float* be0  = (const float*)d_in[12];
    const float* g1   = (const float*)d_in[13];
    const float* be1  = (const float*)d_in[14];
    float* out = (float*)d_out;

    const int* row = ei;
    const int* col = ei + EE;

    float *t1, *t2, *t3, *la, *lb, *lc, *ld;
    float *sum0, *sumsq0, *sum1, *sumsq1;
    int *tick0, *tick1;
    __nv_bfloat16 *w0h, *w0l, *w1h, *w1l, *w2h, *w2l;
    cudaGetSymbolAddress((void**)&t1, g_t1);
    cudaGetSymbolAddress((void**)&t2, g_t2);
    cudaGetSymbolAddress((void**)&t3, g_t3);
    cudaGetSymbolAddress((void**)&la, g_la);
    cudaGetSymbolAddress((void**)&lb, g_lb);
    cudaGetSymbolAddress((void**)&lc, g_lc);
    cudaGetSymbolAddress((void**)&ld, g_ld);
    cudaGetSymbolAddress((void**)&sum0,   g_sum0);
    cudaGetSymbolAddress((void**)&sumsq0, g_sumsq0);
    cudaGetSymbolAddress((void**)&sum1,   g_sum1);
    cudaGetSymbolAddress((void**)&sumsq1, g_sumsq1);
    cudaGetSymbolAddress((void**)&tick0, g_tick0);
    cudaGetSymbolAddress((void**)&tick1, g_tick1);
    cudaGetSymbolAddress((void**)&w0h, g_w0h);
    cudaGetSymbolAddress((void**)&w0l, g_w0l);
    cudaGetSymbolAddress((void**)&w1h, g_w1h);
    cudaGetSymbolAddress((void**)&w1l, g_w1l);
    cudaGetSymbolAddress((void**)&w2h, g_w2h);
    cudaGetSymbolAddress((void**)&w2l, g_w2l);

    const int T = 256;
    float* yh1 = out + (size_t)NN * OUTC;
    float* yh2 = out + (size_t)2 * NN * OUTC;

    // ---- weight pre-split ----
    k_split_w<<<cdiv(INC * HIDC, T), T>>>(W0, w0h, w0l, INC * HIDC);
    k_split_w<<<cdiv(HIDC * HIDC, T), T>>>(W1, w1h, w1l, HIDC * HIDC);
    k_split_w<<<cdiv(HIDC * OUTC, T), T>>>(W2, w2h, w2l, HIDC * OUTC);

    // ---- CSR + normalization ----
    k_init_node<<<cdiv(NN, T), T>>>();
    k_deg_cnt<<<cdiv(EE, T), T>>>(row, ew);
    k_scan1<<<NP, 256>>>();                  // + dinv
    k_scan2<<<1, 256>>>();                   // + zero BN stats & tickets
    k_scan3<<<NP, 256>>>();
    k_scatter<<<cdiv(EE, T), T>>>(row, col, ew);

    dim3 gemm_grid_hid(2, cdiv(NN, 128));   // N=256
    dim3 gemm_grid_out(1, cdiv(NN, 128));   // N=40
    int prop40_grid = cdiv(NN, 8);

    // ---- layer 0: x@W0 -> propagate(+b0) -> BN stats (+ fused finalize) ----
    k_mma_bf16<false><<<gemm_grid_hid, T>>>(NN, HIDC, INC, x, w0h, w0l, t1);
    k_prop256<<<NN, 256>>>(t1, t2, b0);
    k_bn_reduce<<<BN_GRID, HIDC>>>(t2, sum0, sumsq0, g0, be0, tick0);

    // ---- layer 1: relu(bn(t2))@W1 -> propagate(+b1) -> BN stats (+ finalize) ----
    k_mma_bf16<true><<<gemm_grid_hid, T>>>(NN, HIDC, HIDC, t2, w1h, w1l, t1);
    k_prop256<<<NN, 256>>>(t1, t2, b1);
    k_bn_reduce<<<BN_GRID, HIDC>>>(t2, sum1, sumsq1, g1, be1, tick1);

    // ---- output conv: relu(bn(t2))@W2 -> propagate(+b2) -> d_out ----
    k_mma_bf16<true><<<gemm_grid_out, T>>>(NN, OUTC, HIDC, t2, w2h, w2l, t3);
    k_prop40<false><<<prop40_grid, 256>>>(t3, nullptr, out, nullptr, b2);

    // ---- LPA: 3 dual propagates ----
    k_prop40<true><<<prop40_grid, 256>>>(lab, lab2, la, lb, nullptr);
    k_prop40<true><<<prop40_grid, 256>>>(la, lb, lc, ld, nullptr);
    k_prop40<true><<<prop40_grid, 256>>>(lc, ld, yh1, yh2, nullptr);
}